// round 17
// baseline (speedup 1.0000x reference)
#include <cuda_runtime.h>
#include <cuda_fp16.h>
#include <mma.h>

using namespace nvcuda;

#define N_NODES 50000
#define N_EDGES 1600000
#define GEMM_GRID 444
#define N_TILES 3125          // 50000 / 16

// Scratch (device globals — no allocation allowed)
__device__ __align__(16) float g_h32[(size_t)N_NODES * 128];  // projected f32 [N,128]
__device__ int    g_rowptr[N_NODES + 1];                      // CSR offsets (dst sorted)
__device__ __align__(16) __half g_Wh[128 * 128];              // W fp16 row-major [k][c]

__device__ __forceinline__ unsigned int h2_as_u32(__half2 h) {
    union { __half2 h; unsigned int u; } cvt;
    cvt.h = h;
    return cvt.u;
}

// ---------------------------------------------------------------------------
// Kernel 0: W -> fp16 (one-time)
// ---------------------------------------------------------------------------
__global__ void wh_kernel(const float* __restrict__ W) {
    const int i = blockIdx.x * 256 + threadIdx.x;
    if (i < 128 * 128) g_Wh[i] = __float2half(__ldg(&W[i]));
}

// ---------------------------------------------------------------------------
// Kernel 1: h = feat @ W via wmma — persistent blocks, B-frags in registers
// (R15 structure, measured ~15-18us). Epilogue now writes f32 directly
// (cheaper than the old fp16 convert, and removes h-storage rounding).
// ---------------------------------------------------------------------------
__global__ void __launch_bounds__(256) gemm_kernel(const float* __restrict__ feat) {
    __shared__ __align__(16) __half sA[16 * 136];     // padded ldm=136
    __shared__ __align__(16) float sStage[8 * 256];

    const int tid = threadIdx.x;
    const int w = tid >> 5;
    const int l = tid & 31;

    wmma::fragment<wmma::matrix_b, 16, 16, 16, __half, wmma::row_major> B[8];
#pragma unroll
    for (int k = 0; k < 8; k++)
        wmma::load_matrix_sync(B[k], g_Wh + k * 16 * 128 + w * 16, 128);

    for (int t = blockIdx.x; t < N_TILES; t += GEMM_GRID) {
        const int base = t * 16;

        __syncthreads();
        for (int i = tid; i < 512; i += 256) {
            const int r = i >> 5, c4 = i & 31;
            const float4 f = __ldg((const float4*)(feat + (size_t)(base + r) * 128) + c4);
            unsigned int* dp = (unsigned int*)sA + r * 68 + c4 * 2;
            dp[0] = h2_as_u32(__floats2half2_rn(f.x, f.y));
            dp[1] = h2_as_u32(__floats2half2_rn(f.z, f.w));
        }
        __syncthreads();

        wmma::fragment<wmma::accumulator, 16, 16, 16, float> c;
        wmma::fill_fragment(c, 0.0f);
#pragma unroll
        for (int k = 0; k < 8; k++) {
            wmma::fragment<wmma::matrix_a, 16, 16, 16, __half, wmma::row_major> a;
            wmma::load_matrix_sync(a, sA + k * 16, 136);
            wmma::mma_sync(c, a, B[k], c);
        }

        wmma::store_matrix_sync(sStage + w * 256, c, 16, wmma::mem_row_major);
        __syncwarp();
        {
            const int r = l >> 1, c0 = (l & 1) * 8;
            const float4* sp = (const float4*)(sStage + w * 256 + r * 16 + c0);
            float4* dp = (float4*)(g_h32 + (size_t)(base + r) * 128 + w * 16 + c0);
            dp[0] = sp[0];
            dp[1] = sp[1];
        }
        __syncwarp();
    }
}

// ---------------------------------------------------------------------------
// Kernel 2: CSR offsets via binary search (dst is sorted).
// ---------------------------------------------------------------------------
__global__ void rowptr_kernel(const int* __restrict__ dst) {
    const int n = blockIdx.x * blockDim.x + threadIdx.x;
    if (n > N_NODES) return;
    int lo = 0, hi = N_EDGES;
    while (lo < hi) {
        const int mid = (lo + hi) >> 1;
        if (__ldg(&dst[mid]) < n) lo = mid + 1;
        else hi = mid;
    }
    g_rowptr[n] = lo;
}

// ---------------------------------------------------------------------------
// Kernel 3: fused scores + softmax + aggregation. R11 SHAPE (one warp/node,
// 4-edge buffer, 8 lanes/head, scalar f32 math — the shape that held occ=84%)
// with the 4 F2F converts/edge removed by gathering f32 directly (float4/lane,
// 512B/edge; L2 was 26% at 256B so ~55% after doubling — still under cap).
// ~15.5 issues/edge vs ~19. launch_bounds(64,24) caps regs at 42 so the
// R16-style occupancy collapse is structurally impossible.
// ---------------------------------------------------------------------------
__global__ void __launch_bounds__(64, 24) attn_kernel(const int* __restrict__ src,
                                                      float* __restrict__ out) {
    const int n = (int)((blockIdx.x * 64 + threadIdx.x) >> 5);
    const int l = threadIdx.x & 31;
    if (n >= N_NODES) return;

    const int beg = g_rowptr[n];
    const int end = g_rowptr[n + 1];

    const float4* __restrict__ H4 = (const float4*)g_h32;  // 32 float4 per node

    // 1/sqrt(32) * log2(e): fold softmax scale + exp2 conversion into hd
    const float scale_d = 0.17677669529663689f * 1.4426950408889634f;
    float4 hd = H4[(size_t)n * 32 + l];
    hd.x *= scale_d; hd.y *= scale_d; hd.z *= scale_d; hd.w *= scale_d;

    float s = 0.f;
    float4 acc = make_float4(0.f, 0.f, 0.f, 0.f);

#define ATTN_EDGE(a)                                                 \
    {                                                                \
        float d = (a).x * hd.x;                                      \
        d = fmaf((a).y, hd.y, d);                                    \
        d = fmaf((a).z, hd.z, d);                                    \
        d = fmaf((a).w, hd.w, d);                                    \
        d += __shfl_xor_sync(0xffffffffu, d, 1);                     \
        d += __shfl_xor_sync(0xffffffffu, d, 2);                     \
        d += __shfl_xor_sync(0xffffffffu, d, 4);                     \
        const float p = exp2f(d);                                    \
        s += p;                                                      \
        acc.x = fmaf(p, (a).x, acc.x);                               \
        acc.y = fmaf(p, (a).y, acc.y);                               \
        acc.z = fmaf(p, (a).z, acc.z);                               \
        acc.w = fmaf(p, (a).w, acc.w);                               \
    }

    int e = beg;
    const int e_al = min(end, (beg + 3) & ~3);           // align src to int4
    for (; e < e_al; e++) {
        const int sn = __ldg(&src[e]);
        const float4 v = __ldg(&H4[(size_t)sn * 32 + l]);
        ATTN_EDGE(v);
    }
    const int e_main = e_al + ((end - e_al) & ~3);
    for (; e < e_main; e += 4) {
        const int4 sn4 = __ldg((const int4*)(src + e));   // 1 LDG per 4 edges
        float4 v0 = __ldg(&H4[(size_t)sn4.x * 32 + l]);
        float4 v1 = __ldg(&H4[(size_t)sn4.y * 32 + l]);
        float4 v2 = __ldg(&H4[(size_t)sn4.z * 32 + l]);
        float4 v3 = __ldg(&H4[(size_t)sn4.w * 32 + l]);
        ATTN_EDGE(v0);
        ATTN_EDGE(v1);
        ATTN_EDGE(v2);
        ATTN_EDGE(v3);
    }
    for (; e < end; e++) {
        const int sn = __ldg(&src[e]);
        const float4 v = __ldg(&H4[(size_t)sn * 32 + l]);
        ATTN_EDGE(v);
    }
#undef ATTN_EDGE

    const float inv = (s > 0.f) ? (1.0f / s) : 0.f;
    float4 o;
    o.x = acc.x * inv; o.y = acc.y * inv;
    o.z = acc.z * inv; o.w = acc.w * inv;
    ((float4*)out)[(size_t)n * 32 + l] = o;
}

// ---------------------------------------------------------------------------
extern "C" void kernel_launch(void* const* d_in, const int* in_sizes, int n_in,
                              void* d_out, int out_size) {
    const float* feat = (const float*)d_in[0];   // [N, 128] f32
    const int*   src  = (const int*)d_in[1];     // [E] i32
    const int*   dst  = (const int*)d_in[2];     // [E] i32, sorted
    const float* W    = (const float*)d_in[3];   // [128, 128] f32
    float* out = (float*)d_out;                  // [N, 128] f32

    wh_kernel<<<64, 256>>>(W);
    rowptr_kernel<<<(N_NODES + 1 + 255) / 256, 256>>>(dst);
    gemm_kernel<<<GEMM_GRID, 256>>>(feat);
    attn_kernel<<<(N_NODES * 32 + 63) / 64, 64>>>(src, out);
}